// round 7
// baseline (speedup 1.0000x reference)
#include <cuda_runtime.h>
#include <cstdint>

#define CH        151
#define N_EDGES   47
#define RPT       16                     // rows per warp-tile
#define TILE_F    (RPT * CH)             // 2416 floats
#define TILE_V4   (TILE_F / 4)           // 604 float4 (16B-aligned: 2416 % 4 == 0)
#define NWARP     11
#define THREADS   (NWARP * 32)           // 352
#define SMEM_BYTES (NWARP * 2 * TILE_F * 4)   // 212,608 B dynamic

// Skeleton edges, premultiplied by 3 (channel offset of joint)
__constant__ int c_par3[N_EDGES] = {
    0,3,6,9,3,15,18,24,24,24,24,24,27,30,33,39,42,45,51,54,57,63,66,69,
    75,78,81,87,87,87,87,87,90,93,96,102,105,108,114,117,120,126,129,132,138,141,144};
__constant__ int c_chi3[N_EDGES] = {
    3,6,9,87,15,18,24,27,39,51,63,75,30,33,36,42,45,48,54,57,60,66,69,72,
    78,81,84,90,102,114,126,138,93,96,99,105,108,111,117,120,123,129,132,135,141,144,147};

__device__ double g_acc[2];

__global__ void init_acc_kernel() { g_acc[0] = 0.0; g_acc[1] = 0.0; }

// ---- edge-range math for one row, edges [e0, e1) ----
// q = masked preds (precomputed, q = (t!=0) ? p : 0), t = raw targets (== t*mask)
__device__ __forceinline__ void do_edges(const float* __restrict__ q,
                                         const float* __restrict__ t,
                                         const int* __restrict__ s_a,
                                         const int* __restrict__ s_b,
                                         int e0, int e1, float& vel_acc)
{
    float vel = 0.f;
    #pragma unroll 4
    for (int e = e0; e < e1; e++) {
        int a = s_a[e];
        int b = s_b[e];

        float dp0 = q[a]   - q[b];
        float dp1 = q[a+1] - q[b+1];
        float dp2 = q[a+2] - q[b+2];
        float dt0 = t[a]   - t[b];
        float dt1 = t[a+1] - t[b+1];
        float dt2 = t[a+2] - t[b+2];

        float np = fmaf(dp0, dp0, fmaf(dp1, dp1, dp2 * dp2));
        float nt = fmaf(dt0, dt0, fmaf(dt1, dt1, dt2 * dt2));

        // ref: diff/(sqrt(n)+tiny); n==0 -> 0; n>0 -> rsqrt
        float ip = (np > 0.f) ? rsqrtf(np) : 0.f;
        float it = (nt > 0.f) ? rsqrtf(nt) : 0.f;

        float d0 = dp0 * ip - dt0 * it;
        float d1 = dp1 * ip - dt1 * it;
        float d2 = dp2 * ip - dt2 * it;

        // direction mask = raw channel mask at c*47+e (post-transpose layout)
        float m0 = t[e];
        float m1 = t[47 + e];
        float m2 = t[94 + e];

        vel += ((m0 != 0.f) ? d0 * d0 : 0.f)
             + ((m1 != 0.f) ? d1 * d1 : 0.f)
             + ((m2 != 0.f) ? d2 * d2 : 0.f);
    }
    vel_acc += vel;
}

// generic fallback for tail rows (straight from gmem, full row)
__device__ __forceinline__ void process_row_gmem(const float* __restrict__ p,
                                                 const float* __restrict__ t,
                                                 const int* __restrict__ s_a,
                                                 const int* __restrict__ s_b,
                                                 float& l1_acc, float& vel_acc)
{
    float l1 = 0.f;
    float q[CH];
    #pragma unroll 8
    for (int i = 0; i < CH; i++) {
        float tv = t[i];
        float pv = p[i];
        float qv = (tv != 0.f) ? pv : 0.f;
        l1 += fabsf(qv - tv);
        q[i] = qv;
    }
    l1_acc += l1;
    do_edges(q, t, s_a, s_b, 0, N_EDGES, vel_acc);
}

extern __shared__ float smem_dyn[];

__global__ void __launch_bounds__(THREADS, 1)
reg_loss_kernel(const float* __restrict__ preds,
                const float* __restrict__ targets,
                int tiles, int rows)
{
    __shared__ int   s_a[N_EDGES], s_b[N_EDGES];
    __shared__ float s_red[2][NWARP];

    const int lane   = threadIdx.x & 31;
    const int wloc   = threadIdx.x >> 5;
    const int gwarp  = blockIdx.x * NWARP + wloc;
    const int nwarps = gridDim.x * NWARP;

    if (threadIdx.x < N_EDGES) {
        s_a[threadIdx.x] = c_par3[threadIdx.x];
        s_b[threadIdx.x] = c_chi3[threadIdx.x];
    }
    __syncthreads();

    // per-warp private tile: masked preds q + raw targets t
    // row stride 151 (odd) -> conflict-free LDS in edge phase
    float* sQ = smem_dyn + wloc * (2 * TILE_F);
    float* sT = sQ + TILE_F;

    float l1_acc = 0.f, vel_acc = 0.f;

    for (int tile = gwarp; tile < tiles; tile += nwarps) {
        const float4* gp = (const float4*)(preds   + (size_t)tile * TILE_F);
        const float4* gt = (const float4*)(targets + (size_t)tile * TILE_F);
        float4* dQ = (float4*)sQ;
        float4* dT = (float4*)sT;

        // ---- phase A: coalesced load + fused L1 + masking + stage ----
        #pragma unroll 4
        for (int i = lane; i < TILE_V4; i += 32) {
            float4 tv = gt[i];
            float4 pv = gp[i];

            float4 qv;
            qv.x = (tv.x != 0.f) ? pv.x : 0.f;
            qv.y = (tv.y != 0.f) ? pv.y : 0.f;
            qv.z = (tv.z != 0.f) ? pv.z : 0.f;
            qv.w = (tv.w != 0.f) ? pv.w : 0.f;

            // |q - t| == mask * |p - t| (t==0 -> q==0 -> 0)
            l1_acc += fabsf(qv.x - tv.x) + fabsf(qv.y - tv.y)
                    + fabsf(qv.z - tv.z) + fabsf(qv.w - tv.w);

            dQ[i] = qv;
            dT[i] = tv;
        }
        __syncwarp();

        // ---- phase B: edges only; 2 lanes per row (24 + 23 edges) ----
        {
            int row  = lane >> 1;            // 0..15
            int half = lane & 1;
            int e0   = half ? 24 : 0;
            int e1   = half ? N_EDGES : 24;
            const float* q = sQ + row * CH;
            const float* t = sT + row * CH;
            do_edges(q, t, s_a, s_b, e0, e1, vel_acc);
        }
        __syncwarp();   // all lanes done before next tile overwrites
    }

    // tail rows (rows % RPT) straight from gmem (empty for this dataset)
    if (gwarp == 0) {
        for (int row = tiles * RPT + lane; row < rows; row += 32) {
            process_row_gmem(preds + (size_t)row * CH, targets + (size_t)row * CH,
                             s_a, s_b, l1_acc, vel_acc);
        }
    }

    // ---- warp reduce ----
    #pragma unroll
    for (int o = 16; o > 0; o >>= 1) {
        l1_acc  += __shfl_down_sync(0xFFFFFFFFu, l1_acc,  o);
        vel_acc += __shfl_down_sync(0xFFFFFFFFu, vel_acc, o);
    }
    if (lane == 0) { s_red[0][wloc] = l1_acc; s_red[1][wloc] = vel_acc; }
    __syncthreads();

    // ---- block reduce + 2 double atomics per block (296 total) ----
    if (threadIdx.x == 0) {
        float a = 0.f, v = 0.f;
        #pragma unroll
        for (int i = 0; i < NWARP; i++) { a += s_red[0][i]; v += s_red[1][i]; }
        atomicAdd(&g_acc[0], (double)a);
        atomicAdd(&g_acc[1], (double)v);
    }
}

__global__ void finalize_kernel(float* __restrict__ out,
                                double n_l1, double n_vel)
{
    double l1  = g_acc[0] / n_l1;
    double vel = g_acc[1] / n_vel;
    out[0] = (float)(l1 + 0.1 * vel);
}

extern "C" void kernel_launch(void* const* d_in, const int* in_sizes, int n_in,
                              void* d_out, int out_size)
{
    const float* preds   = (const float*)d_in[0];
    const float* targets = (const float*)d_in[1];
    float* out = (float*)d_out;

    int n     = in_sizes[0];
    int rows  = n / CH;            // B*T = 131072
    int tiles = rows / RPT;        // 8192

    cudaFuncSetAttribute(reg_loss_kernel,
                         cudaFuncAttributeMaxDynamicSharedMemorySize, SMEM_BYTES);

    init_acc_kernel<<<1, 1>>>();

    // 148 blocks (1/SM, 212.6KB smem), 11 warps each -> 1628 independent warps
    reg_loss_kernel<<<148, THREADS, SMEM_BYTES>>>(preds, targets, tiles, rows);

    finalize_kernel<<<1, 1>>>(out,
                              (double)rows * (double)CH,
                              (double)rows * (double)(N_EDGES * 3));
}

// round 8
// speedup vs baseline: 1.0894x; 1.0894x over previous
#include <cuda_runtime.h>
#include <cstdint>

#define CH        151
#define N_EDGES   47
#define RPT       8                      // rows per warp-tile
#define TILE_F    (RPT * CH)             // 1208 floats
#define TILE_V4   (TILE_F / 4)           // 302 float4 (tile start 16B-aligned)
#define NWARP     20
#define THREADS   (NWARP * 32)           // 640
#define SMEM_BYTES (NWARP * 2 * TILE_F * 4)   // 193,280 B dynamic

// Skeleton edges, premultiplied by 3 (channel offset of joint)
__constant__ int c_par3[N_EDGES] = {
    0,3,6,9,3,15,18,24,24,24,24,24,27,30,33,39,42,45,51,54,57,63,66,69,
    75,78,81,87,87,87,87,87,90,93,96,102,105,108,114,117,120,126,129,132,138,141,144};
__constant__ int c_chi3[N_EDGES] = {
    3,6,9,87,15,18,24,27,39,51,63,75,30,33,36,42,45,48,54,57,60,66,69,72,
    78,81,84,90,102,114,126,138,93,96,99,105,108,111,117,120,123,129,132,135,141,144,147};

// persistent accumulators; statically zero, and the last block of every
// launch resets them -> identical state at the start of every graph replay
__device__ double   g_acc[2] = {0.0, 0.0};
__device__ unsigned g_ticket = 0;

// ---- edge-range math for one row, edges [e0, e1) ----
// q = masked preds (q = (t!=0) ? p : 0), t = raw targets (== t*mask)
__device__ __forceinline__ void do_edges(const float* __restrict__ q,
                                         const float* __restrict__ t,
                                         const int* __restrict__ s_a,
                                         const int* __restrict__ s_b,
                                         int e0, int e1, float& vel_acc)
{
    float vel = 0.f;
    #pragma unroll 4
    for (int e = e0; e < e1; e++) {
        int a = s_a[e];
        int b = s_b[e];

        float dp0 = q[a]   - q[b];
        float dp1 = q[a+1] - q[b+1];
        float dp2 = q[a+2] - q[b+2];
        float dt0 = t[a]   - t[b];
        float dt1 = t[a+1] - t[b+1];
        float dt2 = t[a+2] - t[b+2];

        float np = fmaf(dp0, dp0, fmaf(dp1, dp1, dp2 * dp2));
        float nt = fmaf(dt0, dt0, fmaf(dt1, dt1, dt2 * dt2));

        // ref: diff/(sqrt(n)+tiny); n==0 -> 0; n>0 -> rsqrt
        float ip = (np > 0.f) ? rsqrtf(np) : 0.f;
        float it = (nt > 0.f) ? rsqrtf(nt) : 0.f;

        float d0 = dp0 * ip - dt0 * it;
        float d1 = dp1 * ip - dt1 * it;
        float d2 = dp2 * ip - dt2 * it;

        // direction mask = raw channel mask at c*47+e (post-transpose layout)
        float m0 = t[e];
        float m1 = t[47 + e];
        float m2 = t[94 + e];

        vel += ((m0 != 0.f) ? d0 * d0 : 0.f)
             + ((m1 != 0.f) ? d1 * d1 : 0.f)
             + ((m2 != 0.f) ? d2 * d2 : 0.f);
    }
    vel_acc += vel;
}

// generic fallback for tail rows (straight from gmem, full row)
__device__ __forceinline__ void process_row_gmem(const float* __restrict__ p,
                                                 const float* __restrict__ t,
                                                 const int* __restrict__ s_a,
                                                 const int* __restrict__ s_b,
                                                 float& l1_acc, float& vel_acc)
{
    float l1 = 0.f;
    float q[CH];
    #pragma unroll 8
    for (int i = 0; i < CH; i++) {
        float tv = t[i];
        float pv = p[i];
        float qv = (tv != 0.f) ? pv : 0.f;
        l1 += fabsf(qv - tv);
        q[i] = qv;
    }
    l1_acc += l1;
    do_edges(q, t, s_a, s_b, 0, N_EDGES, vel_acc);
}

extern __shared__ float smem_dyn[];

__global__ void __launch_bounds__(THREADS, 1)
reg_loss_kernel(const float* __restrict__ preds,
                const float* __restrict__ targets,
                float* __restrict__ out,
                int tiles, int rows)
{
    __shared__ int   s_a[N_EDGES], s_b[N_EDGES];
    __shared__ float s_red[2][NWARP];
    __shared__ bool  s_last;

    const int lane   = threadIdx.x & 31;
    const int wloc   = threadIdx.x >> 5;
    const int gwarp  = blockIdx.x * NWARP + wloc;
    const int nwarps = gridDim.x * NWARP;

    if (threadIdx.x < N_EDGES) {
        s_a[threadIdx.x] = c_par3[threadIdx.x];
        s_b[threadIdx.x] = c_chi3[threadIdx.x];
    }
    __syncthreads();

    // per-warp private tile: masked preds q + raw targets t
    // row stride 151 (odd) -> conflict-free LDS in edge phase
    float* sQ = smem_dyn + wloc * (2 * TILE_F);
    float* sT = sQ + TILE_F;

    float l1_acc = 0.f, vel_acc = 0.f;

    for (int tile = gwarp; tile < tiles; tile += nwarps) {
        const float4* gp = (const float4*)(preds   + (size_t)tile * TILE_F);
        const float4* gt = (const float4*)(targets + (size_t)tile * TILE_F);
        float4* dQ = (float4*)sQ;
        float4* dT = (float4*)sT;

        // ---- phase A: coalesced load + fused L1 + masking + stage ----
        #pragma unroll 5
        for (int i = lane; i < TILE_V4; i += 32) {
            float4 tv = gt[i];
            float4 pv = gp[i];

            float4 qv;
            qv.x = (tv.x != 0.f) ? pv.x : 0.f;
            qv.y = (tv.y != 0.f) ? pv.y : 0.f;
            qv.z = (tv.z != 0.f) ? pv.z : 0.f;
            qv.w = (tv.w != 0.f) ? pv.w : 0.f;

            // |q - t| == mask * |p - t| (t==0 -> q==0 -> 0)
            l1_acc += fabsf(qv.x - tv.x) + fabsf(qv.y - tv.y)
                    + fabsf(qv.z - tv.z) + fabsf(qv.w - tv.w);

            dQ[i] = qv;
            dT[i] = tv;
        }
        __syncwarp();

        // ---- phase B: edges only; 4 lanes per row (12/12/12/11 edges) ----
        {
            int row  = lane >> 2;            // 0..7
            int quad = lane & 3;
            int e0   = quad * 12;
            int e1   = (quad == 3) ? N_EDGES : e0 + 12;
            const float* q = sQ + row * CH;
            const float* t = sT + row * CH;
            do_edges(q, t, s_a, s_b, e0, e1, vel_acc);
        }
        __syncwarp();   // all lanes done before next tile overwrites
    }

    // tail rows (rows % RPT) straight from gmem (empty for this dataset)
    if (gwarp == 0) {
        for (int row = tiles * RPT + lane; row < rows; row += 32) {
            process_row_gmem(preds + (size_t)row * CH, targets + (size_t)row * CH,
                             s_a, s_b, l1_acc, vel_acc);
        }
    }

    // ---- warp reduce ----
    #pragma unroll
    for (int o = 16; o > 0; o >>= 1) {
        l1_acc  += __shfl_down_sync(0xFFFFFFFFu, l1_acc,  o);
        vel_acc += __shfl_down_sync(0xFFFFFFFFu, vel_acc, o);
    }
    if (lane == 0) { s_red[0][wloc] = l1_acc; s_red[1][wloc] = vel_acc; }
    __syncthreads();

    // ---- block reduce + global accumulate + last-block finalize ----
    if (threadIdx.x == 0) {
        float a = 0.f, v = 0.f;
        #pragma unroll
        for (int i = 0; i < NWARP; i++) { a += s_red[0][i]; v += s_red[1][i]; }
        atomicAdd(&g_acc[0], (double)a);
        atomicAdd(&g_acc[1], (double)v);
        __threadfence();
        unsigned t = atomicAdd(&g_ticket, 1u);
        s_last = (t == gridDim.x - 1);
    }
    __syncthreads();

    if (s_last && threadIdx.x == 0) {
        // all blocks' atomics are visible (fence + ticket acquire chain)
        double l1  = g_acc[0] / ((double)rows * (double)CH);
        double vel = g_acc[1] / ((double)rows * (double)(N_EDGES * 3));
        out[0] = (float)(l1 + 0.1 * vel);
        // reset persistent state so every graph replay starts identically
        g_acc[0] = 0.0;
        g_acc[1] = 0.0;
        __threadfence();
        atomicExch(&g_ticket, 0u);
    }
}

extern "C" void kernel_launch(void* const* d_in, const int* in_sizes, int n_in,
                              void* d_out, int out_size)
{
    const float* preds   = (const float*)d_in[0];
    const float* targets = (const float*)d_in[1];
    float* out = (float*)d_out;

    int n     = in_sizes[0];
    int rows  = n / CH;            // B*T = 131072
    int tiles = rows / RPT;        // 16384

    cudaFuncSetAttribute(reg_loss_kernel,
                         cudaFuncAttributeMaxDynamicSharedMemorySize, SMEM_BYTES);

    // ONE launch: 148 blocks (1/SM, 193.3KB smem), 20 warps each
    reg_loss_kernel<<<148, THREADS, SMEM_BYTES>>>(preds, targets, out, tiles, rows);
}